// round 1
// baseline (speedup 1.0000x reference)
#include <cuda_runtime.h>

#define NTOK 4096
#define CCH 512
#define NH 8
#define HD 64
#define MQKV 1536

// Scratch (device globals; no runtime allocation allowed)
__device__ float g_qkv[MQKV * NTOK];   // [3C, N] : rows 0..511 = q*0.125, 512..1023 = k, 1024..1535 = v
__device__ float g_att[CCH * NTOK];    // [C, N] attention output

// Fast exp for x <= 0: 2^(x*log2e) via exponent-bit construction + degree-6 poly.
// Avoids MUFU (chip exp throughput ~133G/s would bottleneck softmax at ~1ms).
__device__ __forceinline__ float fast_exp(float x) {
    float t = fmaxf(x * 1.4426950408889634f, -126.0f);
    float fi = floorf(t);
    float f = t - fi;                      // f in [0,1)
    float p = 1.5403530393381609e-4f;
    p = fmaf(p, f, 1.3333558146428443e-3f);
    p = fmaf(p, f, 9.6181291076284771e-3f);
    p = fmaf(p, f, 5.5504108664821580e-2f);
    p = fmaf(p, f, 2.4022650695910071e-1f);
    p = fmaf(p, f, 6.9314718055994531e-1f);
    p = fmaf(p, f, 1.0f);
    int ei = (int)fi;                      // ei in [-126, 0]
    return __int_as_float((ei + 127) << 23) * p;
}

// ---------------------------------------------------------------------------
// Kernel 1: QKV projection.  Y[m,n] = sum_k W[m,k] * X[k,n], M=1536, K=512, N=4096
// Folds q scale (0.125) into rows m < 512. 64x64 block tile, 4x4 per thread.
// ---------------------------------------------------------------------------
__global__ __launch_bounds__(256) void qkv_gemm(const float* __restrict__ W,
                                                const float* __restrict__ X) {
    __shared__ float As[16 * 68];   // [kk][mm], padded row 68 (16B aligned)
    __shared__ float Bs[16 * 64];   // [kk][nn]
    const int t = threadIdx.x, tx = t & 15, ty = t >> 4;
    const int n0 = blockIdx.x * 64, m0 = blockIdx.y * 64;
    float acc[4][4] = {};

    for (int k0 = 0; k0 < CCH; k0 += 16) {
        __syncthreads();
#pragma unroll
        for (int r = 0; r < 4; r++) {
            int e = r * 256 + t;
            int kk = e & 15, mm = e >> 4;
            As[kk * 68 + mm] = W[(m0 + mm) * CCH + k0 + kk];
            int kk2 = e >> 6, nn = e & 63;
            Bs[kk2 * 64 + nn] = X[(k0 + kk2) * NTOK + n0 + nn];
        }
        __syncthreads();
#pragma unroll
        for (int kk = 0; kk < 16; kk++) {
            float4 a = *(const float4*)(As + kk * 68 + ty * 4);
            float4 b = *(const float4*)(Bs + kk * 64 + tx * 4);
            acc[0][0] = fmaf(a.x, b.x, acc[0][0]); acc[0][1] = fmaf(a.x, b.y, acc[0][1]);
            acc[0][2] = fmaf(a.x, b.z, acc[0][2]); acc[0][3] = fmaf(a.x, b.w, acc[0][3]);
            acc[1][0] = fmaf(a.y, b.x, acc[1][0]); acc[1][1] = fmaf(a.y, b.y, acc[1][1]);
            acc[1][2] = fmaf(a.y, b.z, acc[1][2]); acc[1][3] = fmaf(a.y, b.w, acc[1][3]);
            acc[2][0] = fmaf(a.z, b.x, acc[2][0]); acc[2][1] = fmaf(a.z, b.y, acc[2][1]);
            acc[2][2] = fmaf(a.z, b.z, acc[2][2]); acc[2][3] = fmaf(a.z, b.w, acc[2][3]);
            acc[3][0] = fmaf(a.w, b.x, acc[3][0]); acc[3][1] = fmaf(a.w, b.y, acc[3][1]);
            acc[3][2] = fmaf(a.w, b.z, acc[3][2]); acc[3][3] = fmaf(a.w, b.w, acc[3][3]);
        }
    }
    const float sc = (m0 < 512) ? 0.125f : 1.0f;   // scale q rows (block never straddles)
#pragma unroll
    for (int ii = 0; ii < 4; ii++) {
        int m = m0 + ty * 4 + ii;
        float4 o = make_float4(acc[ii][0] * sc, acc[ii][1] * sc,
                               acc[ii][2] * sc, acc[ii][3] * sc);
        *(float4*)(g_qkv + m * NTOK + n0 + tx * 4) = o;
    }
}

// ---------------------------------------------------------------------------
// Kernel 2: flash attention. One block = 64 queries of one head.
// S tile 64x64 (4x4/thread), online softmax, P overlays K buffer, V XOR-swizzled.
// Exactly 48KB static shared memory.
// ---------------------------------------------------------------------------
__global__ __launch_bounds__(256) void flash_attn() {
    __shared__ float Qs[64 * 64];    // [d][i]
    __shared__ float KPs[64 * 64];   // K: [d][j] during S; then P: [i][j]
    __shared__ float Vs[64 * 64];    // [j][d ^ ((j&15)<<2)]  (swizzled transpose)

    const int t = threadIdx.x, tx = t & 15, ty = t >> 4;
    const int i0 = blockIdx.x * 64;
    const int h  = blockIdx.y;

    const float* qb = g_qkv + (h * HD) * NTOK + i0;
    const float* kb = g_qkv + (CCH + h * HD) * NTOK;
    const float* vb = g_qkv + (2 * CCH + h * HD) * NTOK;

    // Load Q tile [64d x 64i], coalesced on i
#pragma unroll
    for (int r = 0; r < 16; r++) {
        int e = r * 256 + t;
        int d = e >> 6, i = e & 63;
        Qs[d * 64 + i] = qb[d * NTOK + i];
    }

    float O[16] = {};                       // [ii][dd], d = tx*4+dd, i = ty*4+ii
    float mrow[4] = {-1e30f, -1e30f, -1e30f, -1e30f};
    float lrow[4] = {0.f, 0.f, 0.f, 0.f};

    for (int kt = 0; kt < 64; kt++) {
        const int j0 = kt * 64;
        __syncthreads();   // protect KPs/Vs from previous iteration's readers
#pragma unroll
        for (int r = 0; r < 16; r++) {
            int e = r * 256 + t;
            int d = e >> 6, j = e & 63;
            KPs[d * 64 + j] = kb[d * NTOK + j0 + j];
            Vs[j * 64 + (d ^ ((j & 15) << 2))] = vb[d * NTOK + j0 + j];
        }
        __syncthreads();

        // S = Q^T K (q already scaled by 1/8)
        float s[16] = {};
#pragma unroll 8
        for (int d = 0; d < 64; d++) {
            float4 q = *(const float4*)(Qs + d * 64 + ty * 4);
            float4 k = *(const float4*)(KPs + d * 64 + tx * 4);
            s[0]  = fmaf(q.x, k.x, s[0]);  s[1]  = fmaf(q.x, k.y, s[1]);
            s[2]  = fmaf(q.x, k.z, s[2]);  s[3]  = fmaf(q.x, k.w, s[3]);
            s[4]  = fmaf(q.y, k.x, s[4]);  s[5]  = fmaf(q.y, k.y, s[5]);
            s[6]  = fmaf(q.y, k.z, s[6]);  s[7]  = fmaf(q.y, k.w, s[7]);
            s[8]  = fmaf(q.z, k.x, s[8]);  s[9]  = fmaf(q.z, k.y, s[9]);
            s[10] = fmaf(q.z, k.z, s[10]); s[11] = fmaf(q.z, k.w, s[11]);
            s[12] = fmaf(q.w, k.x, s[12]); s[13] = fmaf(q.w, k.y, s[13]);
            s[14] = fmaf(q.w, k.z, s[14]); s[15] = fmaf(q.w, k.w, s[15]);
        }
        __syncthreads();   // all threads done reading K before P overwrites KPs

        // Online softmax per row (row i owned by the 16 lanes sharing ty)
#pragma unroll
        for (int ii = 0; ii < 4; ii++) {
            float mt = fmaxf(fmaxf(s[ii*4+0], s[ii*4+1]), fmaxf(s[ii*4+2], s[ii*4+3]));
#pragma unroll
            for (int off = 1; off < 16; off <<= 1)
                mt = fmaxf(mt, __shfl_xor_sync(0xffffffffu, mt, off));
            float mnew = fmaxf(mrow[ii], mt);
            float corr = fast_exp(mrow[ii] - mnew);
            mrow[ii] = mnew;
            float sum = 0.f;
#pragma unroll
            for (int jj = 0; jj < 4; jj++) {
                float p = fast_exp(s[ii*4+jj] - mnew);
                s[ii*4+jj] = p;
                sum += p;
            }
#pragma unroll
            for (int off = 1; off < 16; off <<= 1)
                sum += __shfl_xor_sync(0xffffffffu, sum, off);
            lrow[ii] = lrow[ii] * corr + sum;
            O[ii*4+0] *= corr; O[ii*4+1] *= corr; O[ii*4+2] *= corr; O[ii*4+3] *= corr;
            *(float4*)(KPs + (ty*4+ii) * 64 + tx*4) =
                make_float4(s[ii*4+0], s[ii*4+1], s[ii*4+2], s[ii*4+3]);
        }
        __syncthreads();

        // O += P @ V^T   (V read swizzled, conflict-free)
#pragma unroll 8
        for (int j = 0; j < 64; j++) {
            float4 v = *(const float4*)(Vs + j * 64 + ((tx ^ (j & 15)) << 2));
#pragma unroll
            for (int ii = 0; ii < 4; ii++) {
                float p = KPs[(ty*4+ii) * 64 + j];
                O[ii*4+0] = fmaf(p, v.x, O[ii*4+0]);
                O[ii*4+1] = fmaf(p, v.y, O[ii*4+1]);
                O[ii*4+2] = fmaf(p, v.z, O[ii*4+2]);
                O[ii*4+3] = fmaf(p, v.w, O[ii*4+3]);
            }
        }
    }

    // Normalize and write out[(h*64+d), i0+i]
#pragma unroll
    for (int ii = 0; ii < 4; ii++) {
        float inv = 1.0f / lrow[ii];
#pragma unroll
        for (int dd = 0; dd < 4; dd++) {
            int d = tx * 4 + dd;
            g_att[(h * HD + d) * NTOK + i0 + ty * 4 + ii] = O[ii*4+dd] * inv;
        }
    }
}

// ---------------------------------------------------------------------------
// Kernel 3: output projection + bias + residual.
// Y[m,n] = sum_c W[m,c]*att[c,n] + b[m] + x[m,n], M=K=512, N=4096
// ---------------------------------------------------------------------------
__global__ __launch_bounds__(256) void out_gemm(const float* __restrict__ W,
                                                const float* __restrict__ bias,
                                                const float* __restrict__ xres,
                                                float* __restrict__ Y) {
    __shared__ float As[16 * 68];
    __shared__ float Bs[16 * 64];
    const int t = threadIdx.x, tx = t & 15, ty = t >> 4;
    const int n0 = blockIdx.x * 64, m0 = blockIdx.y * 64;
    float acc[4][4] = {};

    for (int k0 = 0; k0 < CCH; k0 += 16) {
        __syncthreads();
#pragma unroll
        for (int r = 0; r < 4; r++) {
            int e = r * 256 + t;
            int kk = e & 15, mm = e >> 4;
            As[kk * 68 + mm] = W[(m0 + mm) * CCH + k0 + kk];
            int kk2 = e >> 6, nn = e & 63;
            Bs[kk2 * 64 + nn] = g_att[(k0 + kk2) * NTOK + n0 + nn];
        }
        __syncthreads();
#pragma unroll
        for (int kk = 0; kk < 16; kk++) {
            float4 a = *(const float4*)(As + kk * 68 + ty * 4);
            float4 b = *(const float4*)(Bs + kk * 64 + tx * 4);
            acc[0][0] = fmaf(a.x, b.x, acc[0][0]); acc[0][1] = fmaf(a.x, b.y, acc[0][1]);
            acc[0][2] = fmaf(a.x, b.z, acc[0][2]); acc[0][3] = fmaf(a.x, b.w, acc[0][3]);
            acc[1][0] = fmaf(a.y, b.x, acc[1][0]); acc[1][1] = fmaf(a.y, b.y, acc[1][1]);
            acc[1][2] = fmaf(a.y, b.z, acc[1][2]); acc[1][3] = fmaf(a.y, b.w, acc[1][3]);
            acc[2][0] = fmaf(a.z, b.x, acc[2][0]); acc[2][1] = fmaf(a.z, b.y, acc[2][1]);
            acc[2][2] = fmaf(a.z, b.z, acc[2][2]); acc[2][3] = fmaf(a.z, b.w, acc[2][3]);
            acc[3][0] = fmaf(a.w, b.x, acc[3][0]); acc[3][1] = fmaf(a.w, b.y, acc[3][1]);
            acc[3][2] = fmaf(a.w, b.z, acc[3][2]); acc[3][3] = fmaf(a.w, b.w, acc[3][3]);
        }
    }
#pragma unroll
    for (int ii = 0; ii < 4; ii++) {
        int m = m0 + ty * 4 + ii;
        float bb = bias[m];
        int base = m * NTOK + n0 + tx * 4;
        float4 r = *(const float4*)(xres + base);
        float4 o = make_float4(acc[ii][0] + bb + r.x, acc[ii][1] + bb + r.y,
                               acc[ii][2] + bb + r.z, acc[ii][3] + bb + r.w);
        *(float4*)(Y + base) = o;
    }
}

extern "C" void kernel_launch(void* const* d_in, const int* in_sizes, int n_in,
                              void* d_out, int out_size) {
    const float* x     = (const float*)d_in[0];   // [512, 4096]
    const float* w_qkv = (const float*)d_in[1];   // [1536, 512]
    const float* w_out = (const float*)d_in[2];   // [512, 512]
    const float* b_out = (const float*)d_in[3];   // [512]
    float* out = (float*)d_out;                   // [512, 4096]

    qkv_gemm<<<dim3(64, 24), 256>>>(w_qkv, x);
    flash_attn<<<dim3(64, 8), 256>>>();
    out_gemm<<<dim3(64, 8), 256>>>(w_out, b_out, x, out);
}

// round 2
// speedup vs baseline: 2.2060x; 2.2060x over previous
#include <cuda_runtime.h>
#include <cuda_bf16.h>
#include <cstdint>

#define NTOK 4096
#define CCH 512
#define NH 8
#define HD 64
#define MQKV 1536

// Scratch (device globals; no runtime allocation allowed)
__device__ float g_qkv[MQKV * NTOK];   // [3C, N] rows: 0..511 q*0.125, 512..1023 k, 1024..1535 v
__device__ float g_att[CCH * NTOK];    // [C, N] attention output

// Fast exp for x <= 0 (avoids MUFU bottleneck)
__device__ __forceinline__ float fast_exp(float x) {
    float t = fmaxf(x * 1.4426950408889634f, -126.0f);
    float fi = floorf(t);
    float f = t - fi;
    float p = 1.5403530393381609e-4f;
    p = fmaf(p, f, 1.3333558146428443e-3f);
    p = fmaf(p, f, 9.6181291076284771e-3f);
    p = fmaf(p, f, 5.5504108664821580e-2f);
    p = fmaf(p, f, 2.4022650695910071e-1f);
    p = fmaf(p, f, 6.9314718055994531e-1f);
    p = fmaf(p, f, 1.0f);
    return __int_as_float(((int)fi + 127) << 23) * p;
}

__device__ __forceinline__ uint32_t f2tf32(float x) {
    uint32_t r;
    asm("cvt.rna.tf32.f32 %0, %1;" : "=r"(r) : "f"(x));
    return r;
}
__device__ __forceinline__ uint32_t pack_bf16x2(float lo, float hi) {
    uint32_t r;
    asm("cvt.rn.bf16x2.f32 %0, %1, %2;" : "=r"(r) : "f"(hi), "f"(lo));
    return r;
}
__device__ __forceinline__ void mma_tf32(float c[4], const uint32_t a[4],
                                         uint32_t b0, uint32_t b1) {
    asm volatile(
        "mma.sync.aligned.m16n8k8.row.col.f32.tf32.tf32.f32 "
        "{%0,%1,%2,%3}, {%4,%5,%6,%7}, {%8,%9}, {%0,%1,%2,%3};"
        : "+f"(c[0]), "+f"(c[1]), "+f"(c[2]), "+f"(c[3])
        : "r"(a[0]), "r"(a[1]), "r"(a[2]), "r"(a[3]), "r"(b0), "r"(b1));
}
__device__ __forceinline__ void mma_bf16(float c[4], const uint32_t a[4],
                                         uint32_t b0, uint32_t b1) {
    asm volatile(
        "mma.sync.aligned.m16n8k16.row.col.f32.bf16.bf16.f32 "
        "{%0,%1,%2,%3}, {%4,%5,%6,%7}, {%8,%9}, {%0,%1,%2,%3};"
        : "+f"(c[0]), "+f"(c[1]), "+f"(c[2]), "+f"(c[3])
        : "r"(a[0]), "r"(a[1]), "r"(a[2]), "r"(a[3]), "r"(b0), "r"(b1));
}

// ---------------------------------------------------------------------------
// Kernel 1: QKV projection (fp32 SIMT; converted to mma next round)
// ---------------------------------------------------------------------------
__global__ __launch_bounds__(256) void qkv_gemm(const float* __restrict__ W,
                                                const float* __restrict__ X) {
    __shared__ float As[16 * 68];
    __shared__ float Bs[16 * 64];
    const int t = threadIdx.x, tx = t & 15, ty = t >> 4;
    const int n0 = blockIdx.x * 64, m0 = blockIdx.y * 64;
    float acc[4][4] = {};
    for (int k0 = 0; k0 < CCH; k0 += 16) {
        __syncthreads();
#pragma unroll
        for (int r = 0; r < 4; r++) {
            int e = r * 256 + t;
            int kk = e & 15, mm = e >> 4;
            As[kk * 68 + mm] = W[(m0 + mm) * CCH + k0 + kk];
            int kk2 = e >> 6, nn = e & 63;
            Bs[kk2 * 64 + nn] = X[(k0 + kk2) * NTOK + n0 + nn];
        }
        __syncthreads();
#pragma unroll
        for (int kk = 0; kk < 16; kk++) {
            float4 a = *(const float4*)(As + kk * 68 + ty * 4);
            float4 b = *(const float4*)(Bs + kk * 64 + tx * 4);
            acc[0][0] = fmaf(a.x, b.x, acc[0][0]); acc[0][1] = fmaf(a.x, b.y, acc[0][1]);
            acc[0][2] = fmaf(a.x, b.z, acc[0][2]); acc[0][3] = fmaf(a.x, b.w, acc[0][3]);
            acc[1][0] = fmaf(a.y, b.x, acc[1][0]); acc[1][1] = fmaf(a.y, b.y, acc[1][1]);
            acc[1][2] = fmaf(a.y, b.z, acc[1][2]); acc[1][3] = fmaf(a.y, b.w, acc[1][3]);
            acc[2][0] = fmaf(a.z, b.x, acc[2][0]); acc[2][1] = fmaf(a.z, b.y, acc[2][1]);
            acc[2][2] = fmaf(a.z, b.z, acc[2][2]); acc[2][3] = fmaf(a.z, b.w, acc[2][3]);
            acc[3][0] = fmaf(a.w, b.x, acc[3][0]); acc[3][1] = fmaf(a.w, b.y, acc[3][1]);
            acc[3][2] = fmaf(a.w, b.z, acc[3][2]); acc[3][3] = fmaf(a.w, b.w, acc[3][3]);
        }
    }
    const float sc = (m0 < 512) ? 0.125f : 1.0f;
#pragma unroll
    for (int ii = 0; ii < 4; ii++) {
        int m = m0 + ty * 4 + ii;
        float4 o = make_float4(acc[ii][0] * sc, acc[ii][1] * sc,
                               acc[ii][2] * sc, acc[ii][3] * sc);
        *(float4*)(g_qkv + m * NTOK + n0 + tx * 4) = o;
    }
}

// ---------------------------------------------------------------------------
// Kernel 2: flash attention on tensor cores.
// 128 threads (4 warps). Each warp owns 16 query rows x 64 cols.
// S = Q K^T via tf32 m16n8k8; softmax in C-fragments; O += P V via bf16
// m16n8k16 with direct C-frag -> A-frag register reuse.
// ---------------------------------------------------------------------------
__global__ __launch_bounds__(128) void flash_attn() {
    __shared__ float    Ks[64 * 72];     // K (fp32): [d][j], stride 72
    __shared__ uint32_t Vs32[64 * 36];   // V (bf16x2): [d][j-pair], stride 36 words

    const int t = threadIdx.x;
    const int w = t >> 5;                // warp 0..3 -> rows w*16..w*16+15
    const int lane = t & 31;
    const int g = lane >> 2;             // groupID 0..7
    const int q4 = lane & 3;             // lane%4
    const int i0 = blockIdx.x * 64;
    const int h  = blockIdx.y;

    const float* qrow = g_qkv + (h * HD) * NTOK;             // [d][i]
    const float* krow = g_qkv + (CCH + h * HD) * NTOK;       // [d][j]
    const float* vrow = g_qkv + (2 * CCH + h * HD) * NTOK;   // [d][j]

    // ---- Stage Q tile into Ks, extract tf32 A-fragments (resident for whole loop)
#pragma unroll
    for (int it = 0; it < 16; it++) {
        int e = it * 128 + t;
        int d = e >> 5, j2 = e & 31;
        *(float2*)&Ks[d * 72 + j2 * 2] = *(const float2*)&qrow[d * NTOK + i0 + j2 * 2];
    }
    __syncthreads();

    uint32_t Qa[8][4];
#pragma unroll
    for (int kc = 0; kc < 8; kc++) {
        int base = (kc * 8 + q4) * 72 + w * 16 + g;
        Qa[kc][0] = f2tf32(Ks[base]);
        Qa[kc][1] = f2tf32(Ks[base + 8]);
        Qa[kc][2] = f2tf32(Ks[base + 4 * 72]);
        Qa[kc][3] = f2tf32(Ks[base + 4 * 72 + 8]);
    }

    float O[8][4] = {};
    float m0 = -1e30f, m1 = -1e30f;
    float l0 = 0.f, l1 = 0.f;

    for (int kt = 0; kt < 64; kt++) {
        const int j0 = kt * 64;
        __syncthreads();
        // load K (fp32) and V (bf16, packed pairs), both [d][j] stride 72
#pragma unroll
        for (int it = 0; it < 16; it++) {
            int e = it * 128 + t;
            int d = e >> 5, j2 = e & 31;
            *(float2*)&Ks[d * 72 + j2 * 2] = *(const float2*)&krow[d * NTOK + j0 + j2 * 2];
            float2 v = *(const float2*)&vrow[d * NTOK + j0 + j2 * 2];
            Vs32[d * 36 + j2] = pack_bf16x2(v.x, v.y);
        }
        __syncthreads();

        // ---- S = Q K^T (tf32). S[jt] covers cols jt*8..jt*8+7
        float S[8][4] = {};
#pragma unroll
        for (int kc = 0; kc < 8; kc++) {
            int rb = (kc * 8 + q4) * 72 + g;
#pragma unroll
            for (int jt = 0; jt < 8; jt++) {
                uint32_t b0 = f2tf32(Ks[rb + jt * 8]);
                uint32_t b1 = f2tf32(Ks[rb + 4 * 72 + jt * 8]);
                mma_tf32(S[jt], Qa[kc], b0, b1);
            }
        }

        // ---- online softmax (rows r0 = g, r1 = g+8 within warp strip)
        float mt0 = -1e30f, mt1 = -1e30f;
#pragma unroll
        for (int jt = 0; jt < 8; jt++) {
            mt0 = fmaxf(mt0, fmaxf(S[jt][0], S[jt][1]));
            mt1 = fmaxf(mt1, fmaxf(S[jt][2], S[jt][3]));
        }
        mt0 = fmaxf(mt0, __shfl_xor_sync(0xffffffffu, mt0, 1));
        mt0 = fmaxf(mt0, __shfl_xor_sync(0xffffffffu, mt0, 2));
        mt1 = fmaxf(mt1, __shfl_xor_sync(0xffffffffu, mt1, 1));
        mt1 = fmaxf(mt1, __shfl_xor_sync(0xffffffffu, mt1, 2));
        float mn0 = fmaxf(m0, mt0), mn1 = fmaxf(m1, mt1);
        float c0 = fast_exp(m0 - mn0), c1 = fast_exp(m1 - mn1);
        m0 = mn0; m1 = mn1;

        float s0 = 0.f, s1 = 0.f;
#pragma unroll
        for (int jt = 0; jt < 8; jt++) {
            S[jt][0] = fast_exp(S[jt][0] - mn0);
            S[jt][1] = fast_exp(S[jt][1] - mn0);
            S[jt][2] = fast_exp(S[jt][2] - mn1);
            S[jt][3] = fast_exp(S[jt][3] - mn1);
            s0 += S[jt][0] + S[jt][1];
            s1 += S[jt][2] + S[jt][3];
        }
        s0 += __shfl_xor_sync(0xffffffffu, s0, 1);
        s0 += __shfl_xor_sync(0xffffffffu, s0, 2);
        s1 += __shfl_xor_sync(0xffffffffu, s1, 1);
        s1 += __shfl_xor_sync(0xffffffffu, s1, 2);
        l0 = l0 * c0 + s0;
        l1 = l1 * c1 + s1;
#pragma unroll
        for (int nt = 0; nt < 8; nt++) {
            O[nt][0] *= c0; O[nt][1] *= c0;
            O[nt][2] *= c1; O[nt][3] *= c1;
        }

        // ---- O += P V (bf16). C-frags of tile pair (2k,2k+1) == bf16 A-frag.
#pragma unroll
        for (int kc2 = 0; kc2 < 4; kc2++) {
            uint32_t Pa[4];
            Pa[0] = pack_bf16x2(S[2 * kc2][0],     S[2 * kc2][1]);
            Pa[1] = pack_bf16x2(S[2 * kc2][2],     S[2 * kc2][3]);
            Pa[2] = pack_bf16x2(S[2 * kc2 + 1][0], S[2 * kc2 + 1][1]);
            Pa[3] = pack_bf16x2(S[2 * kc2 + 1][2], S[2 * kc2 + 1][3]);
#pragma unroll
            for (int nt = 0; nt < 8; nt++) {
                int wb = (nt * 8 + g) * 36 + kc2 * 8 + q4;
                mma_bf16(O[nt], Pa, Vs32[wb], Vs32[wb + 4]);
            }
        }
    }

    // ---- normalize, transpose through Ks, coalesced store
    float inv0 = 1.0f / l0, inv1 = 1.0f / l1;
    __syncthreads();
#pragma unroll
    for (int nt = 0; nt < 8; nt++) {
        int d = nt * 8 + q4 * 2;
        int ir = w * 16 + g;
        Ks[d * 72 + ir]             = O[nt][0] * inv0;
        Ks[(d + 1) * 72 + ir]       = O[nt][1] * inv0;
        Ks[d * 72 + ir + 8]         = O[nt][2] * inv1;
        Ks[(d + 1) * 72 + ir + 8]   = O[nt][3] * inv1;
    }
    __syncthreads();
#pragma unroll
    for (int it = 0; it < 32; it++) {
        int e = it * 128 + t;
        int d = e >> 6, i = e & 63;
        g_att[(h * HD + d) * NTOK + i0 + i] = Ks[d * 72 + i];
    }
}

// ---------------------------------------------------------------------------
// Kernel 3: output projection + bias + residual (fp32 SIMT)
// ---------------------------------------------------------------------------
__global__ __launch_bounds__(256) void out_gemm(const float* __restrict__ W,
                                                const float* __restrict__ bias,
                                                const float* __restrict__ xres,
                                                float* __restrict__ Y) {
    __shared__ float As[16 * 68];
    __shared__ float Bs[16 * 64];
    const int t = threadIdx.x, tx = t & 15, ty = t >> 4;
    const int n0 = blockIdx.x * 64, m0 = blockIdx.y * 64;
    float acc[4][4] = {};
    for (int k0 = 0; k0 < CCH; k0 += 16) {
        __syncthreads();
#pragma unroll
        for (int r = 0; r < 4; r++) {
            int e = r * 256 + t;
            int kk = e & 15, mm = e >> 4;
            As[kk * 68 + mm] = W[(m0 + mm) * CCH + k0 + kk];
            int kk2 = e >> 6, nn = e & 63;
            Bs[kk2 * 64 + nn] = g_att[(k0 + kk2) * NTOK + n0 + nn];
        }
        __syncthreads();
#pragma unroll
        for (int kk = 0; kk < 16; kk++) {
            float4 a = *(const float4*)(As + kk * 68 + ty * 4);
            float4 b = *(const float4*)(Bs + kk * 64 + tx * 4);
            acc[0][0] = fmaf(a.x, b.x, acc[0][0]); acc[0][1] = fmaf(a.x, b.y, acc[0][1]);
            acc[0][2] = fmaf(a.x, b.z, acc[0][2]); acc[0][3] = fmaf(a.x, b.w, acc[0][3]);
            acc[1][0] = fmaf(a.y, b.x, acc[1][0]); acc[1][1] = fmaf(a.y, b.y, acc[1][1]);
            acc[1][2] = fmaf(a.y, b.z, acc[1][2]); acc[1][3] = fmaf(a.y, b.w, acc[1][3]);
            acc[2][0] = fmaf(a.z, b.x, acc[2][0]); acc[2][1] = fmaf(a.z, b.y, acc[2][1]);
            acc[2][2] = fmaf(a.z, b.z, acc[2][2]); acc[2][3] = fmaf(a.z, b.w, acc[2][3]);
            acc[3][0] = fmaf(a.w, b.x, acc[3][0]); acc[3][1] = fmaf(a.w, b.y, acc[3][1]);
            acc[3][2] = fmaf(a.w, b.z, acc[3][2]); acc[3][3] = fmaf(a.w, b.w, acc[3][3]);
        }
    }
#pragma unroll
    for (int ii = 0; ii < 4; ii++) {
        int m = m0 + ty * 4 + ii;
        float bb = bias[m];
        int base = m * NTOK + n0 + tx * 4;
        float4 r = *(const float4*)(xres + base);
        float4 o = make_float4(acc[ii][0] + bb + r.x, acc[ii][1] + bb + r.y,
                               acc[ii][2] + bb + r.z, acc[ii][3] + bb + r.w);
        *(float4*)(Y + base) = o;
    }
}

extern "C" void kernel_launch(void* const* d_in, const int* in_sizes, int n_in,
                              void* d_out, int out_size) {
    const float* x     = (const float*)d_in[0];
    const float* w_qkv = (const float*)d_in[1];
    const float* w_out = (const float*)d_in[2];
    const float* b_out = (const float*)d_in[3];
    float* out = (float*)d_out;

    qkv_gemm<<<dim3(64, 24), 256>>>(w_qkv, x);
    flash_attn<<<dim3(64, 8), 128>>>();
    out_gemm<<<dim3(64, 8), 256>>>(w_out, b_out, x, out);
}

// round 3
// speedup vs baseline: 2.8688x; 1.3005x over previous
#include <cuda_runtime.h>
#include <cuda_bf16.h>
#include <cstdint>

#define NTOK 4096
#define CCH 512
#define NH 8
#define HD 64
#define MQKV 1536

// Scratch (device globals; no runtime allocation allowed)
__device__ float g_qkv[MQKV * NTOK];   // [3C, N] rows: 0..511 q*0.125, 512..1023 k, 1024..1535 v
__device__ float g_att[CCH * NTOK];    // [C, N] attention output

// Fast exp for x <= 0 (avoids MUFU bottleneck)
__device__ __forceinline__ float fast_exp(float x) {
    float t = fmaxf(x * 1.4426950408889634f, -126.0f);
    float fi = floorf(t);
    float f = t - fi;
    float p = 1.5403530393381609e-4f;
    p = fmaf(p, f, 1.3333558146428443e-3f);
    p = fmaf(p, f, 9.6181291076284771e-3f);
    p = fmaf(p, f, 5.5504108664821580e-2f);
    p = fmaf(p, f, 2.4022650695910071e-1f);
    p = fmaf(p, f, 6.9314718055994531e-1f);
    p = fmaf(p, f, 1.0f);
    return __int_as_float(((int)fi + 127) << 23) * p;
}

__device__ __forceinline__ uint32_t f2tf32(float x) {
    uint32_t r;
    asm("cvt.rna.tf32.f32 %0, %1;" : "=r"(r) : "f"(x));
    return r;
}
__device__ __forceinline__ float f2tf32f(float x) {
    return __uint_as_float(f2tf32(x));
}
__device__ __forceinline__ uint32_t pack_bf16x2(float lo, float hi) {
    uint32_t r;
    asm("cvt.rn.bf16x2.f32 %0, %1, %2;" : "=r"(r) : "f"(hi), "f"(lo));
    return r;
}
__device__ __forceinline__ void mma_tf32(float c[4], const uint32_t a[4],
                                         uint32_t b0, uint32_t b1) {
    asm volatile(
        "mma.sync.aligned.m16n8k8.row.col.f32.tf32.tf32.f32 "
        "{%0,%1,%2,%3}, {%4,%5,%6,%7}, {%8,%9}, {%0,%1,%2,%3};"
        : "+f"(c[0]), "+f"(c[1]), "+f"(c[2]), "+f"(c[3])
        : "r"(a[0]), "r"(a[1]), "r"(a[2]), "r"(a[3]), "r"(b0), "r"(b1));
}
__device__ __forceinline__ void mma_bf16(float c[4], const uint32_t a[4],
                                         uint32_t b0, uint32_t b1) {
    asm volatile(
        "mma.sync.aligned.m16n8k16.row.col.f32.bf16.bf16.f32 "
        "{%0,%1,%2,%3}, {%4,%5,%6,%7}, {%8,%9}, {%0,%1,%2,%3};"
        : "+f"(c[0]), "+f"(c[1]), "+f"(c[2]), "+f"(c[3])
        : "r"(a[0]), "r"(a[1]), "r"(a[2]), "r"(a[3]), "r"(b0), "r"(b1));
}

// ---------------------------------------------------------------------------
// Tensor-core GEMM: C[M,N] = A[M,512] * B[512,N], N = 4096.
// flags: bit0 = qkv q-scale (m<512 rows *0.125, write g_qkv)
//        bit1 = epilogue bias + residual
//        bit3 = B comes from g_att
// Block 128x128, BK=32, 8 warps (4M x 2N), warp tile 32x64.
// ---------------------------------------------------------------------------
#define STRA 140
#define STRB 136

__global__ __launch_bounds__(256, 2) void gemm_tc(const float* __restrict__ A,
                                                  const float* __restrict__ Bg,
                                                  float* __restrict__ Cg,
                                                  const float* __restrict__ bias,
                                                  const float* __restrict__ res,
                                                  int flags) {
    __shared__ float As[32 * STRA];   // [k][m] tf32
    __shared__ float Bs[32 * STRB];   // [k][n] tf32

    const float* B = (flags & 8) ? g_att : Bg;
    float* C = (flags & 1) ? g_qkv : Cg;

    const int t = threadIdx.x, lane = t & 31, w = t >> 5;
    const int g = lane >> 2, q4 = lane & 3;
    const int mw = (w >> 1) * 32;          // warp m-offset in tile
    const int nw = (w & 1) * 64;           // warp n-offset in tile
    const int m0 = blockIdx.y * 128, n0 = blockIdx.x * 128;

    float c[2][8][4] = {};

    const int mm = t >> 3, kq = (t & 7) * 4;   // A staging coords
    const int kb = t >> 5;                     // B staging row

    for (int k0 = 0; k0 < 512; k0 += 32) {
        __syncthreads();
#pragma unroll
        for (int r = 0; r < 4; r++) {          // A: [m][k] -> As[k][m] (tf32)
            int m = mm + r * 32;
            float4 a4 = *(const float4*)&A[(m0 + m) * 512 + k0 + kq];
            As[(kq + 0) * STRA + m] = f2tf32f(a4.x);
            As[(kq + 1) * STRA + m] = f2tf32f(a4.y);
            As[(kq + 2) * STRA + m] = f2tf32f(a4.z);
            As[(kq + 3) * STRA + m] = f2tf32f(a4.w);
        }
#pragma unroll
        for (int r = 0; r < 4; r++) {          // B: [k][n] -> Bs[k][n] (tf32)
            int k = kb + r * 8;
            float4 b4 = *(const float4*)&B[(k0 + k) * NTOK + n0 + lane * 4];
            float4 cv = make_float4(f2tf32f(b4.x), f2tf32f(b4.y),
                                    f2tf32f(b4.z), f2tf32f(b4.w));
            *(float4*)&Bs[k * STRB + lane * 4] = cv;
        }
        __syncthreads();

#pragma unroll
        for (int kk = 0; kk < 32; kk += 8) {
            uint32_t af[2][4], bf[8][2];
            int ar = (kk + q4) * STRA + mw + g;
#pragma unroll
            for (int mt = 0; mt < 2; mt++) {
                af[mt][0] = __float_as_uint(As[ar + mt * 16]);
                af[mt][1] = __float_as_uint(As[ar + mt * 16 + 8]);
                af[mt][2] = __float_as_uint(As[ar + 4 * STRA + mt * 16]);
                af[mt][3] = __float_as_uint(As[ar + 4 * STRA + mt * 16 + 8]);
            }
            int br = (kk + q4) * STRB + nw + g;
#pragma unroll
            for (int jt = 0; jt < 8; jt++) {
                bf[jt][0] = __float_as_uint(Bs[br + jt * 8]);
                bf[jt][1] = __float_as_uint(Bs[br + 4 * STRB + jt * 8]);
            }
#pragma unroll
            for (int mt = 0; mt < 2; mt++)
#pragma unroll
                for (int jt = 0; jt < 8; jt++)
                    mma_tf32(c[mt][jt], af[mt], bf[jt][0], bf[jt][1]);
        }
    }

    const float sc = ((flags & 1) && m0 < 512) ? 0.125f : 1.0f;
#pragma unroll
    for (int mt = 0; mt < 2; mt++) {
#pragma unroll
        for (int jt = 0; jt < 8; jt++) {
            int row = m0 + mw + mt * 16 + g;
            int col = n0 + nw + jt * 8 + q4 * 2;
            float2 lo = make_float2(c[mt][jt][0] * sc, c[mt][jt][1] * sc);
            float2 hi = make_float2(c[mt][jt][2] * sc, c[mt][jt][3] * sc);
            if (flags & 2) {
                float b0v = bias[row], b1v = bias[row + 8];
                float2 r0 = *(const float2*)&res[row * NTOK + col];
                float2 r1 = *(const float2*)&res[(row + 8) * NTOK + col];
                lo.x += b0v + r0.x; lo.y += b0v + r0.y;
                hi.x += b1v + r1.x; hi.y += b1v + r1.y;
            }
            *(float2*)&C[row * NTOK + col] = lo;
            *(float2*)&C[(row + 8) * NTOK + col] = hi;
        }
    }
}

// ---------------------------------------------------------------------------
// Kernel 2: flash attention on tensor cores (unchanged from round 2).
// ---------------------------------------------------------------------------
__global__ __launch_bounds__(128) void flash_attn() {
    __shared__ float    Ks[64 * 72];
    __shared__ uint32_t Vs32[64 * 36];

    const int t = threadIdx.x;
    const int w = t >> 5;
    const int lane = t & 31;
    const int g = lane >> 2;
    const int q4 = lane & 3;
    const int i0 = blockIdx.x * 64;
    const int h  = blockIdx.y;

    const float* qrow = g_qkv + (h * HD) * NTOK;
    const float* krow = g_qkv + (CCH + h * HD) * NTOK;
    const float* vrow = g_qkv + (2 * CCH + h * HD) * NTOK;

#pragma unroll
    for (int it = 0; it < 16; it++) {
        int e = it * 128 + t;
        int d = e >> 5, j2 = e & 31;
        *(float2*)&Ks[d * 72 + j2 * 2] = *(const float2*)&qrow[d * NTOK + i0 + j2 * 2];
    }
    __syncthreads();

    uint32_t Qa[8][4];
#pragma unroll
    for (int kc = 0; kc < 8; kc++) {
        int base = (kc * 8 + q4) * 72 + w * 16 + g;
        Qa[kc][0] = f2tf32(Ks[base]);
        Qa[kc][1] = f2tf32(Ks[base + 8]);
        Qa[kc][2] = f2tf32(Ks[base + 4 * 72]);
        Qa[kc][3] = f2tf32(Ks[base + 4 * 72 + 8]);
    }

    float O[8][4] = {};
    float m0 = -1e30f, m1 = -1e30f;
    float l0 = 0.f, l1 = 0.f;

    for (int kt = 0; kt < 64; kt++) {
        const int j0 = kt * 64;
        __syncthreads();
#pragma unroll
        for (int it = 0; it < 16; it++) {
            int e = it * 128 + t;
            int d = e >> 5, j2 = e & 31;
            *(float2*)&Ks[d * 72 + j2 * 2] = *(const float2*)&krow[d * NTOK + j0 + j2 * 2];
            float2 v = *(const float2*)&vrow[d * NTOK + j0 + j2 * 2];
            Vs32[d * 36 + j2] = pack_bf16x2(v.x, v.y);
        }
        __syncthreads();

        float S[8][4] = {};
#pragma unroll
        for (int kc = 0; kc < 8; kc++) {
            int rb = (kc * 8 + q4) * 72 + g;
#pragma unroll
            for (int jt = 0; jt < 8; jt++) {
                uint32_t b0 = f2tf32(Ks[rb + jt * 8]);
                uint32_t b1 = f2tf32(Ks[rb + 4 * 72 + jt * 8]);
                mma_tf32(S[jt], Qa[kc], b0, b1);
            }
        }

        float mt0 = -1e30f, mt1 = -1e30f;
#pragma unroll
        for (int jt = 0; jt < 8; jt++) {
            mt0 = fmaxf(mt0, fmaxf(S[jt][0], S[jt][1]));
            mt1 = fmaxf(mt1, fmaxf(S[jt][2], S[jt][3]));
        }
        mt0 = fmaxf(mt0, __shfl_xor_sync(0xffffffffu, mt0, 1));
        mt0 = fmaxf(mt0, __shfl_xor_sync(0xffffffffu, mt0, 2));
        mt1 = fmaxf(mt1, __shfl_xor_sync(0xffffffffu, mt1, 1));
        mt1 = fmaxf(mt1, __shfl_xor_sync(0xffffffffu, mt1, 2));
        float mn0 = fmaxf(m0, mt0), mn1 = fmaxf(m1, mt1);
        float c0 = fast_exp(m0 - mn0), c1 = fast_exp(m1 - mn1);
        m0 = mn0; m1 = mn1;

        float s0 = 0.f, s1 = 0.f;
#pragma unroll
        for (int jt = 0; jt < 8; jt++) {
            S[jt][0] = fast_exp(S[jt][0] - mn0);
            S[jt][1] = fast_exp(S[jt][1] - mn0);
            S[jt][2] = fast_exp(S[jt][2] - mn1);
            S[jt][3] = fast_exp(S[jt][3] - mn1);
            s0 += S[jt][0] + S[jt][1];
            s1 += S[jt][2] + S[jt][3];
        }
        s0 += __shfl_xor_sync(0xffffffffu, s0, 1);
        s0 += __shfl_xor_sync(0xffffffffu, s0, 2);
        s1 += __shfl_xor_sync(0xffffffffu, s1, 1);
        s1 += __shfl_xor_sync(0xffffffffu, s1, 2);
        l0 = l0 * c0 + s0;
        l1 = l1 * c1 + s1;
#pragma unroll
        for (int nt = 0; nt < 8; nt++) {
            O[nt][0] *= c0; O[nt][1] *= c0;
            O[nt][2] *= c1; O[nt][3] *= c1;
        }

#pragma unroll
        for (int kc2 = 0; kc2 < 4; kc2++) {
            uint32_t Pa[4];
            Pa[0] = pack_bf16x2(S[2 * kc2][0],     S[2 * kc2][1]);
            Pa[1] = pack_bf16x2(S[2 * kc2][2],     S[2 * kc2][3]);
            Pa[2] = pack_bf16x2(S[2 * kc2 + 1][0], S[2 * kc2 + 1][1]);
            Pa[3] = pack_bf16x2(S[2 * kc2 + 1][2], S[2 * kc2 + 1][3]);
#pragma unroll
            for (int nt = 0; nt < 8; nt++) {
                int wb = (nt * 8 + g) * 36 + kc2 * 8 + q4;
                mma_bf16(O[nt], Pa, Vs32[wb], Vs32[wb + 4]);
            }
        }
    }

    float inv0 = 1.0f / l0, inv1 = 1.0f / l1;
    __syncthreads();
#pragma unroll
    for (int nt = 0; nt < 8; nt++) {
        int d = nt * 8 + q4 * 2;
        int ir = w * 16 + g;
        Ks[d * 72 + ir]           = O[nt][0] * inv0;
        Ks[(d + 1) * 72 + ir]     = O[nt][1] * inv0;
        Ks[d * 72 + ir + 8]       = O[nt][2] * inv1;
        Ks[(d + 1) * 72 + ir + 8] = O[nt][3] * inv1;
    }
    __syncthreads();
#pragma unroll
    for (int it = 0; it < 32; it++) {
        int e = it * 128 + t;
        int d = e >> 6, i = e & 63;
        g_att[(h * HD + d) * NTOK + i0 + i] = Ks[d * 72 + i];
    }
}

extern "C" void kernel_launch(void* const* d_in, const int* in_sizes, int n_in,
                              void* d_out, int out_size) {
    const float* x     = (const float*)d_in[0];
    const float* w_qkv = (const float*)d_in[1];
    const float* w_out = (const float*)d_in[2];
    const float* b_out = (const float*)d_in[3];
    float* out = (float*)d_out;

    // QKV projection: M=1536 -> grid.y=12; writes g_qkv with q-scale
    gemm_tc<<<dim3(32, 12), 256>>>(w_qkv, x, nullptr, nullptr, nullptr, /*flags=*/1);
    flash_attn<<<dim3(64, 8), 128>>>();
    // Output projection: M=512 -> grid.y=4; B=g_att, epilogue bias+residual
    gemm_tc<<<dim3(32, 4), 256>>>(w_out, nullptr, out, b_out, x, /*flags=*/2 | 8);
}

// round 4
// speedup vs baseline: 4.5676x; 1.5921x over previous
#include <cuda_runtime.h>
#include <cuda_bf16.h>
#include <cstdint>

#define NTOK 4096
#define CCH 512
#define NH 8
#define HD 64
#define MQKV 1536

// Scratch (device globals; no runtime allocation allowed)
__device__ float g_qkv[MQKV * NTOK];   // rows 0..511 = q*0.125*log2e, 512..1023 = k, 1024..1535 = v
__device__ float g_att[CCH * NTOK];    // [C, N] attention output

__device__ __forceinline__ uint32_t f2tf32(float x) {
    uint32_t r;
    asm("cvt.rna.tf32.f32 %0, %1;" : "=r"(r) : "f"(x));
    return r;
}
__device__ __forceinline__ float f2tf32f(float x) {
    return __uint_as_float(f2tf32(x));
}
__device__ __forceinline__ uint32_t pack_bf16x2(float lo, float hi) {
    uint32_t r;
    asm("cvt.rn.bf16x2.f32 %0, %1, %2;" : "=r"(r) : "f"(hi), "f"(lo));
    return r;
}
__device__ __forceinline__ float exp2_fast(float x) {
    float y;
    asm("ex2.approx.ftz.f32 %0, %1;" : "=f"(y) : "f"(x));
    return y;
}
__device__ __forceinline__ void mma_tf32(float c[4], const uint32_t a[4],
                                         uint32_t b0, uint32_t b1) {
    asm volatile(
        "mma.sync.aligned.m16n8k8.row.col.f32.tf32.tf32.f32 "
        "{%0,%1,%2,%3}, {%4,%5,%6,%7}, {%8,%9}, {%0,%1,%2,%3};"
        : "+f"(c[0]), "+f"(c[1]), "+f"(c[2]), "+f"(c[3])
        : "r"(a[0]), "r"(a[1]), "r"(a[2]), "r"(a[3]), "r"(b0), "r"(b1));
}
__device__ __forceinline__ void mma_bf16(float c[4], const uint32_t a[4],
                                         uint32_t b0, uint32_t b1) {
    asm volatile(
        "mma.sync.aligned.m16n8k16.row.col.f32.bf16.bf16.f32 "
        "{%0,%1,%2,%3}, {%4,%5,%6,%7}, {%8,%9}, {%0,%1,%2,%3};"
        : "+f"(c[0]), "+f"(c[1]), "+f"(c[2]), "+f"(c[3])
        : "r"(a[0]), "r"(a[1]), "r"(a[2]), "r"(a[3]), "r"(b0), "r"(b1));
}

// ---------------------------------------------------------------------------
// Tensor-core GEMM (unchanged except q-scale now folds log2e for exp2 softmax)
// ---------------------------------------------------------------------------
#define STRA 140
#define STRB 136

__global__ __launch_bounds__(256, 2) void gemm_tc(const float* __restrict__ A,
                                                  const float* __restrict__ Bg,
                                                  float* __restrict__ Cg,
                                                  const float* __restrict__ bias,
                                                  const float* __restrict__ res,
                                                  int flags) {
    __shared__ float As[32 * STRA];
    __shared__ float Bs[32 * STRB];

    const float* B = (flags & 8) ? g_att : Bg;
    float* C = (flags & 1) ? g_qkv : Cg;

    const int t = threadIdx.x, lane = t & 31, w = t >> 5;
    const int g = lane >> 2, q4 = lane & 3;
    const int mw = (w >> 1) * 32;
    const int nw = (w & 1) * 64;
    const int m0 = blockIdx.y * 128, n0 = blockIdx.x * 128;

    float c[2][8][4] = {};

    const int mm = t >> 3, kq = (t & 7) * 4;
    const int kb = t >> 5;

    for (int k0 = 0; k0 < 512; k0 += 32) {
        __syncthreads();
#pragma unroll
        for (int r = 0; r < 4; r++) {
            int m = mm + r * 32;
            float4 a4 = *(const float4*)&A[(m0 + m) * 512 + k0 + kq];
            As[(kq + 0) * STRA + m] = f2tf32f(a4.x);
            As[(kq + 1) * STRA + m] = f2tf32f(a4.y);
            As[(kq + 2) * STRA + m] = f2tf32f(a4.z);
            As[(kq + 3) * STRA + m] = f2tf32f(a4.w);
        }
#pragma unroll
        for (int r = 0; r < 4; r++) {
            int k = kb + r * 8;
            float4 b4 = *(const float4*)&B[(k0 + k) * NTOK + n0 + lane * 4];
            float4 cv = make_float4(f2tf32f(b4.x), f2tf32f(b4.y),
                                    f2tf32f(b4.z), f2tf32f(b4.w));
            *(float4*)&Bs[k * STRB + lane * 4] = cv;
        }
        __syncthreads();

#pragma unroll
        for (int kk = 0; kk < 32; kk += 8) {
            uint32_t af[2][4], bf[8][2];
            int ar = (kk + q4) * STRA + mw + g;
#pragma unroll
            for (int mt = 0; mt < 2; mt++) {
                af[mt][0] = __float_as_uint(As[ar + mt * 16]);
                af[mt][1] = __float_as_uint(As[ar + mt * 16 + 8]);
                af[mt][2] = __float_as_uint(As[ar + 4 * STRA + mt * 16]);
                af[mt][3] = __float_as_uint(As[ar + 4 * STRA + mt * 16 + 8]);
            }
            int br = (kk + q4) * STRB + nw + g;
#pragma unroll
            for (int jt = 0; jt < 8; jt++) {
                bf[jt][0] = __float_as_uint(Bs[br + jt * 8]);
                bf[jt][1] = __float_as_uint(Bs[br + 4 * STRB + jt * 8]);
            }
#pragma unroll
            for (int mt = 0; mt < 2; mt++)
#pragma unroll
                for (int jt = 0; jt < 8; jt++)
                    mma_tf32(c[mt][jt], af[mt], bf[jt][0], bf[jt][1]);
        }
    }

    // q rows scaled by hd^-0.5 * log2(e) so softmax can use exp2
    const float sc = ((flags & 1) && m0 < 512) ? 0.18033688011112042f : 1.0f;
#pragma unroll
    for (int mt = 0; mt < 2; mt++) {
#pragma unroll
        for (int jt = 0; jt < 8; jt++) {
            int row = m0 + mw + mt * 16 + g;
            int col = n0 + nw + jt * 8 + q4 * 2;
            float2 lo = make_float2(c[mt][jt][0] * sc, c[mt][jt][1] * sc);
            float2 hi = make_float2(c[mt][jt][2] * sc, c[mt][jt][3] * sc);
            if (flags & 2) {
                float b0v = bias[row], b1v = bias[row + 8];
                float2 r0 = *(const float2*)&res[row * NTOK + col];
                float2 r1 = *(const float2*)&res[(row + 8) * NTOK + col];
                lo.x += b0v + r0.x; lo.y += b0v + r0.y;
                hi.x += b1v + r1.x; hi.y += b1v + r1.y;
            }
            *(float2*)&C[row * NTOK + col] = lo;
            *(float2*)&C[(row + 8) * NTOK + col] = hi;
        }
    }
}

// ---------------------------------------------------------------------------
// Flash attention, BM=128 (8 warps), fragment-major smem, exp2 softmax.
// Warp w owns rows i0 + w*16 .. +15. Per iter: 64 keys.
// Kf: tf32 K in frag-major layout w/ XOR(q4) swizzle -> LDS.128 frag loads.
// Vf: bf16x2 V frag-major -> LDS.64 frag loads.
// ---------------------------------------------------------------------------
__global__ __launch_bounds__(256, 2) void flash_attn() {
    __shared__ __align__(16) float Kf[32 * 128];   // 16 KB
    __shared__ uint32_t Vf[64 * 40];               // 10 KB

    const int t = threadIdx.x;
    const int w = t >> 5;
    const int lane = t & 31;
    const int g = lane >> 2;
    const int q4 = lane & 3;
    const int i0 = blockIdx.x * 128;
    const int h  = blockIdx.y;

    const float* qrow = g_qkv + (h * HD) * NTOK;
    const float* krow = g_qkv + (CCH + h * HD) * NTOK;
    const float* vrow = g_qkv + (2 * CCH + h * HD) * NTOK;

    // ---- Q fragments straight from global (once)
    uint32_t Qa[8][4];
    {
        const float* qb = qrow + i0 + w * 16 + g;
#pragma unroll
        for (int kc = 0; kc < 8; kc++) {
            int kr = (kc * 8 + q4) * NTOK;
            Qa[kc][0] = f2tf32(qb[kr]);
            Qa[kc][1] = f2tf32(qb[kr + 8]);
            Qa[kc][2] = f2tf32(qb[kr + 4 * NTOK]);
            Qa[kc][3] = f2tf32(qb[kr + 4 * NTOK + 8]);
        }
    }

    // ---- staging constants
    const int ks = w * 8 + (lane >> 2);            // K row this thread stages
    const int q4s = ks & 3;
    const int halfs = (lane >> 4) & 1;
    const float* srcK = krow + ks * NTOK + (lane & 3) * 4;
    int dK[4];
#pragma unroll
    for (int it = 0; it < 4; it++) {
        int jt = ((lane & 3) + 4 * it) >> 1;
        dK[it] = (w * 4 + q4s) * 128 + (lane & 1) * 64
               + (((2 * halfs + (jt >> 2)) ^ q4s) << 2) + (jt & 3);
    }
    const float* srcV = vrow + w * NTOK + lane * 2;
    const int dVbase = w * 40 + (lane >> 3) * 8 + (lane & 3) * 2 + ((lane >> 2) & 1);

    float O[8][4] = {};
    float m0 = -1e30f, m1 = -1e30f;
    float l0 = 0.f, l1 = 0.f;

    for (int kt = 0; kt < 64; kt++) {
        const int j0 = kt * 64;
        __syncthreads();
        // ---- stage K (tf32, frag-major scatter) and V (bf16x2, frag-major)
#pragma unroll
        for (int it = 0; it < 4; it++) {
            float4 a = *(const float4*)(srcK + j0 + 16 * it);
            int d0 = dK[it];
            Kf[d0]      = f2tf32f(a.x);
            Kf[d0 + 16] = f2tf32f(a.y);
            Kf[d0 + 32] = f2tf32f(a.z);
            Kf[d0 + 48] = f2tf32f(a.w);
        }
#pragma unroll
        for (int it = 0; it < 8; it++) {
            float2 v = *(const float2*)(srcV + j0 + 8 * NTOK * it);
            Vf[dVbase + 320 * it] = pack_bf16x2(v.x, v.y);
        }
        __syncthreads();

        // ---- S = Q K^T (tf32), frag-major LDS.128 B loads
        float S[8][4] = {};
#pragma unroll
        for (int kc = 0; kc < 8; kc++) {
            const float4* kp = (const float4*)(Kf + (kc * 4 + q4) * 128 + g * 16);
            float4 L0 = kp[0 ^ q4], L1 = kp[1 ^ q4], L2 = kp[2 ^ q4], L3 = kp[3 ^ q4];
            mma_tf32(S[0], Qa[kc], __float_as_uint(L0.x), __float_as_uint(L2.x));
            mma_tf32(S[1], Qa[kc], __float_as_uint(L0.y), __float_as_uint(L2.y));
            mma_tf32(S[2], Qa[kc], __float_as_uint(L0.z), __float_as_uint(L2.z));
            mma_tf32(S[3], Qa[kc], __float_as_uint(L0.w), __float_as_uint(L2.w));
            mma_tf32(S[4], Qa[kc], __float_as_uint(L1.x), __float_as_uint(L3.x));
            mma_tf32(S[5], Qa[kc], __float_as_uint(L1.y), __float_as_uint(L3.y));
            mma_tf32(S[6], Qa[kc], __float_as_uint(L1.z), __float_as_uint(L3.z));
            mma_tf32(S[7], Qa[kc], __float_as_uint(L1.w), __float_as_uint(L3.w));
        }

        // ---- online softmax (log2 domain, MUFU exp2)
        float mt0 = -1e30f, mt1 = -1e30f;
#pragma unroll
        for (int jt = 0; jt < 8; jt++) {
            mt0 = fmaxf(mt0, fmaxf(S[jt][0], S[jt][1]));
            mt1 = fmaxf(mt1, fmaxf(S[jt][2], S[jt][3]));
        }
        mt0 = fmaxf(mt0, __shfl_xor_sync(0xffffffffu, mt0, 1));
        mt0 = fmaxf(mt0, __shfl_xor_sync(0xffffffffu, mt0, 2));
        mt1 = fmaxf(mt1, __shfl_xor_sync(0xffffffffu, mt1, 1));
        mt1 = fmaxf(mt1, __shfl_xor_sync(0xffffffffu, mt1, 2));
        float mn0 = fmaxf(m0, mt0), mn1 = fmaxf(m1, mt1);
        float c0 = exp2_fast(m0 - mn0), c1 = exp2_fast(m1 - mn1);
        m0 = mn0; m1 = mn1;

        float s0 = 0.f, s1 = 0.f;
#pragma unroll
        for (int jt = 0; jt < 8; jt++) {
            S[jt][0] = exp2_fast(S[jt][0] - mn0);
            S[jt][1] = exp2_fast(S[jt][1] - mn0);
            S[jt][2] = exp2_fast(S[jt][2] - mn1);
            S[jt][3] = exp2_fast(S[jt][3] - mn1);
            s0 += S[jt][0] + S[jt][1];
            s1 += S[jt][2] + S[jt][3];
        }
        s0 += __shfl_xor_sync(0xffffffffu, s0, 1);
        s0 += __shfl_xor_sync(0xffffffffu, s0, 2);
        s1 += __shfl_xor_sync(0xffffffffu, s1, 1);
        s1 += __shfl_xor_sync(0xffffffffu, s1, 2);
        l0 = l0 * c0 + s0;
        l1 = l1 * c1 + s1;
#pragma unroll
        for (int nt = 0; nt < 8; nt++) {
            O[nt][0] *= c0; O[nt][1] *= c0;
            O[nt][2] *= c1; O[nt][3] *= c1;
        }

        // ---- O += P V (bf16), C-frag -> A-frag register reuse; LDS.64 B loads
#pragma unroll
        for (int kc2 = 0; kc2 < 4; kc2++) {
            uint32_t Pa[4];
            Pa[0] = pack_bf16x2(S[2 * kc2][0],     S[2 * kc2][1]);
            Pa[1] = pack_bf16x2(S[2 * kc2][2],     S[2 * kc2][3]);
            Pa[2] = pack_bf16x2(S[2 * kc2 + 1][0], S[2 * kc2 + 1][1]);
            Pa[3] = pack_bf16x2(S[2 * kc2 + 1][2], S[2 * kc2 + 1][3]);
#pragma unroll
            for (int nt = 0; nt < 8; nt++) {
                uint2 bv = *(const uint2*)(Vf + (nt * 8 + g) * 40 + kc2 * 8 + q4 * 2);
                mma_bf16(O[nt], Pa, bv.x, bv.y);
            }
        }
    }

    // ---- normalize + store (scalar, 4-sector coalesced per warp op)
    float inv0 = 1.0f / l0, inv1 = 1.0f / l1;
#pragma unroll
    for (int nt = 0; nt < 8; nt++) {
        float* p = g_att + (h * HD + nt * 8 + q4 * 2) * NTOK + i0 + w * 16 + g;
        p[0]        = O[nt][0] * inv0;
        p[NTOK]     = O[nt][1] * inv0;
        p[8]        = O[nt][2] * inv1;
        p[NTOK + 8] = O[nt][3] * inv1;
    }
}

extern "C" void kernel_launch(void* const* d_in, const int* in_sizes, int n_in,
                              void* d_out, int out_size) {
    const float* x     = (const float*)d_in[0];
    const float* w_qkv = (const float*)d_in[1];
    const float* w_out = (const float*)d_in[2];
    const float* b_out = (const float*)d_in[3];
    float* out = (float*)d_out;

    gemm_tc<<<dim3(32, 12), 256>>>(w_qkv, x, nullptr, nullptr, nullptr, /*flags=*/1);
    flash_attn<<<dim3(32, 8), 256>>>();
    gemm_tc<<<dim3(32, 4), 256>>>(w_out, nullptr, out, b_out, x, /*flags=*/2 | 8);
}